// round 12
// baseline (speedup 1.0000x reference)
#include <cuda_runtime.h>
#include <cuda.h>
#include <cuda_fp16.h>
#include <cstdint>
#include <cstddef>

// ============================================================================
// Problem dims
// ============================================================================
#define TOKENS 8192
#define DIN    2048
#define DOUT   8192

// GEMM tiling — FP16 mma.sync m16n8k16, 4 warps x (64x64), persistent CTAs
#define BM 128
#define BN 128
#define BK 64                    // 64 halves = 128B row = swizzle atom
#define NSTAGE 3
#define NK (DIN/BK)              // 32
#define NTILES ((TOKENS/BM)*(DOUT/BN))   // 4096

#define NWARP_M 2
#define NWARP_N 2
#define WM (BM/NWARP_M)          // 64
#define WN (BN/NWARP_N)          // 64
#define NTHREADS 128             // 4 compute warps

#define A_STAGE_BYTES (BM*BK*2)              // 16384
#define B_STAGE_BYTES (BN*BK*2)              // 16384
#define STAGE_BYTES   (A_STAGE_BYTES + B_STAGE_BYTES)  // 32768
#define SMEM_TOTAL    (NSTAGE*STAGE_BYTES)   // 98304 -> 2 CTAs/SM

#define NCHUNK 8                 // 16B chunks per thread per stage (A and B each)

// ============================================================================
// Scratch
// ============================================================================
__device__ __half g_A[(size_t)TOKENS * DIN];   // 32 MiB, FWHT output (fp16)
__device__ __half g_B[(size_t)DOUT   * DIN];   // 32 MiB, W in fp16 (exact)

// ============================================================================
// Helpers
// ============================================================================
__device__ __forceinline__ uint32_t smem_to_u32(const void* p) {
    uint32_t a;
    asm("{ .reg .u64 t; cvta.to.shared.u64 t, %1; cvt.u32.u64 %0, t; }" : "=r"(a) : "l"(p));
    return a;
}

__device__ __forceinline__ void cpasync16(uint32_t dst, const __half* src) {
    asm volatile("cp.async.cg.shared.global [%0], [%1], 16;" :: "r"(dst), "l"(src));
}

__device__ __forceinline__ void ldsm_x4(uint32_t* r, uint32_t addr) {
    asm volatile("ldmatrix.sync.aligned.m8n8.x4.shared.b16 {%0,%1,%2,%3}, [%4];"
        : "=r"(r[0]), "=r"(r[1]), "=r"(r[2]), "=r"(r[3]) : "r"(addr));
}

__device__ __forceinline__ void mma_f16(float* c, const uint32_t* a, const uint32_t* b) {
    asm volatile(
        "mma.sync.aligned.m16n8k16.row.col.f32.f16.f16.f32 "
        "{%0,%1,%2,%3}, {%4,%5,%6,%7}, {%8,%9}, {%0,%1,%2,%3};"
        : "+f"(c[0]), "+f"(c[1]), "+f"(c[2]), "+f"(c[3])
        : "r"(a[0]), "r"(a[1]), "r"(a[2]), "r"(a[3]), "r"(b[0]), "r"(b[1]));
}

// group-swizzled tile -> (m0, n0), GROUP_M=8 for L2 locality
__device__ __forceinline__ void tile_mn(int t, int& m0, int& n0) {
    const int num_n = DOUT / BN;     // 64
    const int GROUP_M = 8;
    int per_grp = GROUP_M * num_n;   // 512
    int g = t / per_grp;
    int pid_m = g * GROUP_M + (t % per_grp) % GROUP_M;
    int pid_n = (t % per_grp) / GROUP_M;
    m0 = pid_m * BM;
    n0 = pid_n * BN;
}

// ============================================================================
// Kernel 1 (fused prep): blocks [0, TOKENS) per-row FWHT -> fp16 g_A;
// blocks [TOKENS, TOKENS+WCONV_BLOCKS) convert W fp32 -> fp16 g_B.
// ============================================================================
#define WCONV_BLOCKS ((DOUT*DIN/4)/256)   // 16384 blocks, 1 float4 per thread

__global__ void __launch_bounds__(256) prep_kernel(const float* __restrict__ x,
                                                   const float4* __restrict__ w4,
                                                   __half* __restrict__ A,
                                                   __half* __restrict__ B) {
    if (blockIdx.x >= TOKENS) {
        size_t i = (size_t)(blockIdx.x - TOKENS) * 256 + threadIdx.x;
        float4 v = w4[i];
        __half2 p0 = __floats2half2_rn(v.x, v.y);
        __half2 p1 = __floats2half2_rn(v.z, v.w);
        __half2* dst = reinterpret_cast<__half2*>(B + i * 4);
        dst[0] = p0;
        dst[1] = p1;
        return;
    }
    __shared__ float s[DIN];
    const int t = threadIdx.x;
    const int lane = t & 31;
    const float* xr = x + (size_t)blockIdx.x * DIN;

    float v[8];
    #pragma unroll
    for (int e = 0; e < 8; e++) v[e] = xr[t + 256 * e];
    #pragma unroll
    for (int hb = 1; hb <= 4; hb <<= 1) {       // h = 256,512,1024
        #pragma unroll
        for (int e = 0; e < 8; e++) {
            if (!(e & hb)) {
                float a = v[e], b = v[e | hb];
                v[e] = a + b;
                v[e | hb] = a - b;
            }
        }
    }
    #pragma unroll
    for (int e = 0; e < 8; e++) s[t + 256 * e] = v[e];
    __syncthreads();
    {
        float4 f0 = *reinterpret_cast<const float4*>(&s[8 * t]);
        float4 f1 = *reinterpret_cast<const float4*>(&s[8 * t + 4]);
        v[0] = f0.x; v[1] = f0.y; v[2] = f0.z; v[3] = f0.w;
        v[4] = f1.x; v[5] = f1.y; v[6] = f1.z; v[7] = f1.w;
    }
    #pragma unroll
    for (int hb = 1; hb <= 4; hb <<= 1) {       // h = 1,2,4
        #pragma unroll
        for (int e = 0; e < 8; e++) {
            if (!(e & hb)) {
                float a = v[e], b = v[e | hb];
                v[e] = a + b;
                v[e | hb] = a - b;
            }
        }
    }
    #pragma unroll
    for (int mask = 1; mask <= 16; mask <<= 1) { // h = 8..128
        #pragma unroll
        for (int e = 0; e < 8; e++) {
            float o = __shfl_xor_sync(0xFFFFFFFFu, v[e], mask);
            v[e] = (lane & mask) ? (o - v[e]) : (v[e] + o);
        }
    }
    const float scale = 0.022097086912079608f;  // 1/sqrt(2048)
    __half2 h[4];
    #pragma unroll
    for (int e = 0; e < 4; e++)
        h[e] = __floats2half2_rn(v[2 * e] * scale, v[2 * e + 1] * scale);
    *reinterpret_cast<uint4*>(A + (size_t)blockIdx.x * DIN + 8 * t) =
        *reinterpret_cast<uint4*>(h);
}

// ============================================================================
// Kernel 2: persistent FP16 GEMM — continuous cp.async chunk stream across
// tiles (pipeline never drains; no per-tile refill bubble).
//   out[t][o] = sum_k A[t][k] * W[o][k] + bias[o]
//   smem: physical_byte(row, colbyte) = row*128 + (colbyte ^ ((row&7)*16))
// ============================================================================
__global__ void __launch_bounds__(NTHREADS, 2)
gemm_kernel(const __half* __restrict__ Ag,
            const __half* __restrict__ Wg,
            const float* __restrict__ bias,
            float* __restrict__ out) {
    extern __shared__ char smem[];
    const uint32_t sb = smem_to_u32(smem);
    const int tid = threadIdx.x, wid = tid >> 5, lane = tid & 31;
    const int lr = lane >> 2, lc = lane & 3;

    // -------- per-thread cp.async geometry (chunk j: +16j*DIN src, +2048j dst)
    const int r0 = tid >> 3, c16 = tid & 7;
    const size_t srcOff = (size_t)r0 * DIN + c16 * 8;
    const uint32_t dst0 = (uint32_t)(r0 * 128 + ((c16 * 16) ^ ((r0 & 7) * 16)));

    // -------- producer state (runs 2 chunks ahead, across tiles) ------------
    int p_tile = blockIdx.x;
    int p_m0, p_n0;
    tile_mn(p_tile, p_m0, p_n0);
    const __half* pA = Ag + (size_t)p_m0 * DIN + srcOff;
    const __half* pB = Wg + (size_t)p_n0 * DIN + srcOff;
    int p_ki = 0;

    // prologue: chunks 0,1 of first tile
    #pragma unroll
    for (int pre = 0; pre < NSTAGE - 1; pre++) {
        const uint32_t stg = sb + pre * STAGE_BYTES;
        const int koff = p_ki * BK;
        #pragma unroll
        for (int j = 0; j < NCHUNK; j++)
            cpasync16(stg + dst0 + 2048 * j, pA + (size_t)16 * j * DIN + koff);
        #pragma unroll
        for (int j = 0; j < NCHUNK; j++)
            cpasync16(stg + A_STAGE_BYTES + dst0 + 2048 * j,
                      pB + (size_t)16 * j * DIN + koff);
        asm volatile("cp.async.commit_group;" ::: "memory");
        p_ki++;
    }

    // -------- ldmatrix lane addressing --------------------------------------
    const int wm0 = (wid & 1) * WM;      // 0/64
    const int wn0 = (wid >> 1) * WN;     // 0/64
    const int r8 = lane & 7;
    const uint32_t maskL = (uint32_t)(r8 * 16);
    const uint32_t aHi16 = (uint32_t)(((lane >> 4) & 1) * 16);
    const uint32_t aRowByte = (uint32_t)((wm0 + ((lane >> 3) & 1) * 8 + r8) * 128);
    const uint32_t bHi16 = (uint32_t)(((lane >> 3) & 1) * 16);
    const uint32_t bRowByte =
        (uint32_t)(A_STAGE_BYTES + (wn0 + ((lane >> 4) & 1) * 8 + r8) * 128);

    float acc[WM / 16][WN / 8][4];   // [4][8][4] = 128 regs
    #pragma unroll
    for (int mt = 0; mt < WM / 16; mt++)
        #pragma unroll
        for (int nt = 0; nt < WN / 8; nt++)
            #pragma unroll
            for (int q = 0; q < 4; q++) acc[mt][nt][q] = 0.0f;

    int slot = 0;
    int slot2 = NSTAGE - 1;

    // -------- persistent tile loop ------------------------------------------
    for (int tile = blockIdx.x; tile < NTILES; tile += gridDim.x) {
        int m0, n0;
        tile_mn(tile, m0, n0);

        for (int ki = 0; ki < NK; ki++) {
            asm volatile("cp.async.wait_group %0;" :: "n"(NSTAGE - 2) : "memory");
            __syncthreads();

            const uint32_t stg = sb + slot * STAGE_BYTES;
            #pragma unroll
            for (int kk = 0; kk < BK / 16; kk++) {
                const uint32_t aCol = ((uint32_t)(kk * 32) + aHi16) ^ maskL;
                const uint32_t bCol = ((uint32_t)(kk * 32) + bHi16) ^ maskL;
                uint32_t afr[WM / 16][4];
                uint32_t bfr[WN / 8][2];
                #pragma unroll
                for (int mt = 0; mt < WM / 16; mt++)
                    ldsm_x4(afr[mt], stg + aRowByte + mt * 2048 + aCol);
                #pragma unroll
                for (int p = 0; p < WN / 16; p++)
                    ldsm_x4(&bfr[2 * p][0], stg + bRowByte + p * 2048 + bCol);
                #pragma unroll
                for (int mt = 0; mt < WM / 16; mt++)
                    #pragma unroll
                    for (int nt = 0; nt < WN / 8; nt++)
                        mma_f16(acc[mt][nt], afr[mt], bfr[nt]);
            }

            // ---- produce next chunk of the continuous stream ----
            if (p_ki == NK) {                    // advance producer tile
                p_tile += gridDim.x;
                p_ki = 0;
                if (p_tile < NTILES) {
                    tile_mn(p_tile, p_m0, p_n0);
                    pA = Ag + (size_t)p_m0 * DIN + srcOff;
                    pB = Wg + (size_t)p_n0 * DIN + srcOff;
                }
            }
            if (p_tile < NTILES) {
                const uint32_t stg2 = sb + slot2 * STAGE_BYTES;
                const int koff = p_ki * BK;
                #pragma unroll
                for (int j = 0; j < NCHUNK; j++)
                    cpasync16(stg2 + dst0 + 2048 * j, pA + (size_t)16 * j * DIN + koff);
                #pragma unroll
                for (int j = 0; j < NCHUNK; j++)
                    cpasync16(stg2 + A_STAGE_BYTES + dst0 + 2048 * j,
                              pB + (size_t)16 * j * DIN + koff);
                p_ki++;
            }
            // commit (possibly empty) to keep wait_group counts consistent
            asm volatile("cp.async.commit_group;" ::: "memory");

            if (++slot == NSTAGE) slot = 0;
            if (++slot2 == NSTAGE) slot2 = 0;
        }

        // ---- epilogue: bias + store, then reset acc (pipeline stays live) --
        #pragma unroll
        for (int mt = 0; mt < WM / 16; mt++) {
            const int row0 = m0 + wm0 + mt * 16 + lr;
            float* o0 = out + (size_t)row0 * DOUT;
            float* o1 = o0 + (size_t)8 * DOUT;
            #pragma unroll
            for (int nt = 0; nt < WN / 8; nt++) {
                const int col = n0 + wn0 + nt * 8 + 2 * lc;
                const float2 bv = *reinterpret_cast<const float2*>(&bias[col]);
                float2 v0, v1;
                v0.x = acc[mt][nt][0] + bv.x;  v0.y = acc[mt][nt][1] + bv.y;
                v1.x = acc[mt][nt][2] + bv.x;  v1.y = acc[mt][nt][3] + bv.y;
                *reinterpret_cast<float2*>(o0 + col) = v0;
                *reinterpret_cast<float2*>(o1 + col) = v1;
                acc[mt][nt][0] = 0.0f; acc[mt][nt][1] = 0.0f;
                acc[mt][nt][2] = 0.0f; acc[mt][nt][3] = 0.0f;
            }
        }
    }
}

// ============================================================================
// Host launch
// ============================================================================
extern "C" void kernel_launch(void* const* d_in, const int* in_sizes, int n_in,
                              void* d_out, int out_size) {
    const float* x    = (const float*)d_in[0];
    const float* w    = (const float*)d_in[1];
    const float* bias = (const float*)d_in[2];
    float* out        = (float*)d_out;

    __half *dA = nullptr, *dB = nullptr;
    cudaGetSymbolAddress((void**)&dA, g_A);
    cudaGetSymbolAddress((void**)&dB, g_B);

    // 1) fused FWHT + W-conversion
    prep_kernel<<<TOKENS + WCONV_BLOCKS, 256>>>(x, (const float4*)w, dA, dB);

    // 2) persistent GEMM: exactly 2 CTAs per SM
    int nsm = 148;
    cudaDeviceGetAttribute(&nsm, cudaDevAttrMultiProcessorCount, 0);
    cudaFuncSetAttribute(gemm_kernel, cudaFuncAttributeMaxDynamicSharedMemorySize, SMEM_TOTAL);
    gemm_kernel<<<2 * nsm, NTHREADS, SMEM_TOTAL>>>(dA, dB, bias, out);
}

// round 13
// speedup vs baseline: 1.0461x; 1.0461x over previous
#include <cuda_runtime.h>
#include <cuda.h>
#include <cuda_fp16.h>
#include <cstdint>
#include <cstddef>

// ============================================================================
// Problem dims
// ============================================================================
#define TOKENS 8192
#define DIN    2048
#define DOUT   8192

// GEMM tiling — FP16 mma.sync m16n8k16, 4 warps x (64x64), 2 CTAs/SM
#define BM 128
#define BN 128
#define BK 64                    // 64 halves = 128B row = swizzle atom
#define NSTAGE 3
#define NK (DIN/BK)              // 32

#define NWARP_M 2
#define NWARP_N 2
#define WM (BM/NWARP_M)          // 64
#define WN (BN/NWARP_N)          // 64
#define NTHREADS 128             // 4 compute warps

#define A_STAGE_BYTES (BM*BK*2)              // 16384
#define B_STAGE_BYTES (BN*BK*2)              // 16384
#define STAGE_BYTES   (A_STAGE_BYTES + B_STAGE_BYTES)  // 32768
#define SMEM_TOTAL    (NSTAGE*STAGE_BYTES)   // 98304 -> 2 CTAs/SM

#define NCHUNK 8                 // 16B chunks per thread per stage (A and B each)

// ============================================================================
// Scratch
// ============================================================================
__device__ __half g_A[(size_t)TOKENS * DIN];   // 32 MiB, FWHT output (fp16)
__device__ __half g_B[(size_t)DOUT   * DIN];   // 32 MiB, W in fp16 (exact)

// ============================================================================
// Helpers
// ============================================================================
__device__ __forceinline__ uint32_t smem_to_u32(const void* p) {
    uint32_t a;
    asm("{ .reg .u64 t; cvta.to.shared.u64 t, %1; cvt.u32.u64 %0, t; }" : "=r"(a) : "l"(p));
    return a;
}

__device__ __forceinline__ void cpasync16(uint32_t dst, const __half* src) {
    asm volatile("cp.async.cg.shared.global [%0], [%1], 16;" :: "r"(dst), "l"(src));
}

__device__ __forceinline__ void ldsm_x4(uint32_t* r, uint32_t addr) {
    asm volatile("ldmatrix.sync.aligned.m8n8.x4.shared.b16 {%0,%1,%2,%3}, [%4];"
        : "=r"(r[0]), "=r"(r[1]), "=r"(r[2]), "=r"(r[3]) : "r"(addr));
}

__device__ __forceinline__ void mma_f16(float* c, const uint32_t* a, const uint32_t* b) {
    asm volatile(
        "mma.sync.aligned.m16n8k16.row.col.f32.f16.f16.f32 "
        "{%0,%1,%2,%3}, {%4,%5,%6,%7}, {%8,%9}, {%0,%1,%2,%3};"
        : "+f"(c[0]), "+f"(c[1]), "+f"(c[2]), "+f"(c[3])
        : "r"(a[0]), "r"(a[1]), "r"(a[2]), "r"(a[3]), "r"(b[0]), "r"(b[1]));
}

// ============================================================================
// Kernel 1 (fused prep): blocks [0, TOKENS) per-row FWHT -> fp16 g_A;
// blocks [TOKENS, TOKENS+WCONV_BLOCKS) convert W fp32 -> fp16 g_B.
// ============================================================================
#define WCONV_BLOCKS ((DOUT*DIN/4)/256)   // 16384 blocks, 1 float4 per thread

__global__ void __launch_bounds__(256) prep_kernel(const float* __restrict__ x,
                                                   const float4* __restrict__ w4,
                                                   __half* __restrict__ A,
                                                   __half* __restrict__ B) {
    if (blockIdx.x >= TOKENS) {
        size_t i = (size_t)(blockIdx.x - TOKENS) * 256 + threadIdx.x;
        float4 v = w4[i];
        __half2 p0 = __floats2half2_rn(v.x, v.y);
        __half2 p1 = __floats2half2_rn(v.z, v.w);
        __half2* dst = reinterpret_cast<__half2*>(B + i * 4);
        dst[0] = p0;
        dst[1] = p1;
        return;
    }
    __shared__ float s[DIN];
    const int t = threadIdx.x;
    const int lane = t & 31;
    const float* xr = x + (size_t)blockIdx.x * DIN;

    float v[8];
    #pragma unroll
    for (int e = 0; e < 8; e++) v[e] = xr[t + 256 * e];
    #pragma unroll
    for (int hb = 1; hb <= 4; hb <<= 1) {       // h = 256,512,1024
        #pragma unroll
        for (int e = 0; e < 8; e++) {
            if (!(e & hb)) {
                float a = v[e], b = v[e | hb];
                v[e] = a + b;
                v[e | hb] = a - b;
            }
        }
    }
    #pragma unroll
    for (int e = 0; e < 8; e++) s[t + 256 * e] = v[e];
    __syncthreads();
    {
        float4 f0 = *reinterpret_cast<const float4*>(&s[8 * t]);
        float4 f1 = *reinterpret_cast<const float4*>(&s[8 * t + 4]);
        v[0] = f0.x; v[1] = f0.y; v[2] = f0.z; v[3] = f0.w;
        v[4] = f1.x; v[5] = f1.y; v[6] = f1.z; v[7] = f1.w;
    }
    #pragma unroll
    for (int hb = 1; hb <= 4; hb <<= 1) {       // h = 1,2,4
        #pragma unroll
        for (int e = 0; e < 8; e++) {
            if (!(e & hb)) {
                float a = v[e], b = v[e | hb];
                v[e] = a + b;
                v[e | hb] = a - b;
            }
        }
    }
    #pragma unroll
    for (int mask = 1; mask <= 16; mask <<= 1) { // h = 8..128
        #pragma unroll
        for (int e = 0; e < 8; e++) {
            float o = __shfl_xor_sync(0xFFFFFFFFu, v[e], mask);
            v[e] = (lane & mask) ? (o - v[e]) : (v[e] + o);
        }
    }
    const float scale = 0.022097086912079608f;  // 1/sqrt(2048)
    __half2 h[4];
    #pragma unroll
    for (int e = 0; e < 4; e++)
        h[e] = __floats2half2_rn(v[2 * e] * scale, v[2 * e + 1] * scale);
    *reinterpret_cast<uint4*>(A + (size_t)blockIdx.x * DIN + 8 * t) =
        *reinterpret_cast<uint4*>(h);
}

// ============================================================================
// Kernel 2: FP16 GEMM — cp.async 3-stage + ldmatrix with fragment
// double-buffering (LDSM latency hidden under the MMA burst) and early
// producer issue (loads get a full iteration of slack).
//   out[t][o] = sum_k A[t][k] * W[o][k] + bias[o]
//   smem: physical_byte(row, colbyte) = row*128 + (colbyte ^ ((row&7)*16))
// ============================================================================
__global__ void __launch_bounds__(NTHREADS, 2)
gemm_kernel(const __half* __restrict__ Ag,
            const __half* __restrict__ Wg,
            const float* __restrict__ bias,
            float* __restrict__ out) {
    extern __shared__ char smem[];
    const uint32_t sb = smem_to_u32(smem);
    const int tid = threadIdx.x, wid = tid >> 5, lane = tid & 31;
    const int lr = lane >> 2, lc = lane & 3;

    // group-swizzled tile mapping (GROUP_M=8 for L2 locality)
    const int num_n = DOUT / BN;     // 64
    const int GROUP_M = 8;
    int bid = blockIdx.x;
    int per_grp = GROUP_M * num_n;   // 512
    int g = bid / per_grp;
    int pid_m = g * GROUP_M + (bid % per_grp) % GROUP_M;
    int pid_n = (bid % per_grp) / GROUP_M;
    const int m0 = pid_m * BM;
    const int n0 = pid_n * BN;

    // -------- cp.async base addresses (chunk j: +16j*DIN src, +2048j dst) ---
    const int r0 = tid >> 3, c16 = tid & 7;
    const __half* srcA0 = Ag + (size_t)(m0 + r0) * DIN + c16 * 8;
    const __half* srcB0 = Wg + (size_t)(n0 + r0) * DIN + c16 * 8;
    const uint32_t dst0 = (uint32_t)(r0 * 128 + ((c16 * 16) ^ ((r0 & 7) * 16)));

    // -------- prologue: fill stages 0..NSTAGE-2 ------------------------------
    #pragma unroll
    for (int pre = 0; pre < NSTAGE - 1; pre++) {
        const uint32_t stg = sb + pre * STAGE_BYTES;
        const int koff = pre * BK;
        #pragma unroll
        for (int j = 0; j < NCHUNK; j++)
            cpasync16(stg + dst0 + 2048 * j, srcA0 + (size_t)16 * j * DIN + koff);
        #pragma unroll
        for (int j = 0; j < NCHUNK; j++)
            cpasync16(stg + A_STAGE_BYTES + dst0 + 2048 * j,
                      srcB0 + (size_t)16 * j * DIN + koff);
        asm volatile("cp.async.commit_group;" ::: "memory");
    }

    // -------- ldmatrix lane addressing --------------------------------------
    const int wm0 = (wid & 1) * WM;      // 0/64
    const int wn0 = (wid >> 1) * WN;     // 0/64
    const int r8 = lane & 7;
    const uint32_t maskL = (uint32_t)(r8 * 16);
    const uint32_t aHi16 = (uint32_t)(((lane >> 4) & 1) * 16);
    const uint32_t aRowByte = (uint32_t)((wm0 + ((lane >> 3) & 1) * 8 + r8) * 128);
    const uint32_t bHi16 = (uint32_t)(((lane >> 3) & 1) * 16);
    const uint32_t bRowByte =
        (uint32_t)(A_STAGE_BYTES + (wn0 + ((lane >> 4) & 1) * 8 + r8) * 128);

    float acc[WM / 16][WN / 8][4];   // [4][8][4] = 128 regs
    #pragma unroll
    for (int mt = 0; mt < WM / 16; mt++)
        #pragma unroll
        for (int nt = 0; nt < WN / 8; nt++)
            #pragma unroll
            for (int q = 0; q < 4; q++) acc[mt][nt][q] = 0.0f;

    // fragment double buffers
    uint32_t afr[2][WM / 16][4];
    uint32_t bfr[2][WN / 8][2];

    // -------- main loop ------------------------------------------------------
    int slot = 0;
    int slot2 = NSTAGE - 1;
    for (int ki = 0; ki < NK; ki++) {
        asm volatile("cp.async.wait_group %0;" :: "n"(NSTAGE - 2) : "memory");
        __syncthreads();

        // ---- early producer issue: chunk ki+2 into the slot freed last iter
        const int nk2 = ki + NSTAGE - 1;
        if (nk2 < NK) {
            const uint32_t stg2 = sb + slot2 * STAGE_BYTES;
            const int koff = nk2 * BK;
            #pragma unroll
            for (int j = 0; j < NCHUNK; j++)
                cpasync16(stg2 + dst0 + 2048 * j, srcA0 + (size_t)16 * j * DIN + koff);
            #pragma unroll
            for (int j = 0; j < NCHUNK; j++)
                cpasync16(stg2 + A_STAGE_BYTES + dst0 + 2048 * j,
                          srcB0 + (size_t)16 * j * DIN + koff);
        }
        asm volatile("cp.async.commit_group;" ::: "memory");

        const uint32_t stg = sb + slot * STAGE_BYTES;
        // ---- prefetch fragments for kk = 0 ----
        {
            const uint32_t aCol = aHi16 ^ maskL;
            const uint32_t bCol = bHi16 ^ maskL;
            #pragma unroll
            for (int mt = 0; mt < WM / 16; mt++)
                ldsm_x4(afr[0][mt], stg + aRowByte + mt * 2048 + aCol);
            #pragma unroll
            for (int p = 0; p < WN / 16; p++)
                ldsm_x4(&bfr[0][2 * p][0], stg + bRowByte + p * 2048 + bCol);
        }
        #pragma unroll
        for (int kk = 0; kk < BK / 16; kk++) {
            const int cur = kk & 1, nxt = cur ^ 1;
            if (kk < BK / 16 - 1) {      // load kk+1 fragments under kk's MMAs
                const uint32_t aCol = ((uint32_t)((kk + 1) * 32) + aHi16) ^ maskL;
                const uint32_t bCol = ((uint32_t)((kk + 1) * 32) + bHi16) ^ maskL;
                #pragma unroll
                for (int mt = 0; mt < WM / 16; mt++)
                    ldsm_x4(afr[nxt][mt], stg + aRowByte + mt * 2048 + aCol);
                #pragma unroll
                for (int p = 0; p < WN / 16; p++)
                    ldsm_x4(&bfr[nxt][2 * p][0], stg + bRowByte + p * 2048 + bCol);
            }
            #pragma unroll
            for (int mt = 0; mt < WM / 16; mt++)
                #pragma unroll
                for (int nt = 0; nt < WN / 8; nt++)
                    mma_f16(acc[mt][nt], afr[cur][mt], bfr[cur][nt]);
        }

        if (++slot == NSTAGE) slot = 0;
        if (++slot2 == NSTAGE) slot2 = 0;
    }

    // -------- epilogue: bias + store ----------------------------------------
    #pragma unroll
    for (int mt = 0; mt < WM / 16; mt++) {
        const int row0 = m0 + wm0 + mt * 16 + lr;
        float* o0 = out + (size_t)row0 * DOUT;
        float* o1 = o0 + (size_t)8 * DOUT;
        #pragma unroll
        for (int nt = 0; nt < WN / 8; nt++) {
            const int col = n0 + wn0 + nt * 8 + 2 * lc;
            const float2 bv = *reinterpret_cast<const float2*>(&bias[col]);
            float2 v0, v1;
            v0.x = acc[mt][nt][0] + bv.x;  v0.y = acc[mt][nt][1] + bv.y;
            v1.x = acc[mt][nt][2] + bv.x;  v1.y = acc[mt][nt][3] + bv.y;
            *reinterpret_cast<float2*>(o0 + col) = v0;
            *reinterpret_cast<float2*>(o1 + col) = v1;
        }
    }
}

// ============================================================================
// Host launch
// ============================================================================
extern "C" void kernel_launch(void* const* d_in, const int* in_sizes, int n_in,
                              void* d_out, int out_size) {
    const float* x    = (const float*)d_in[0];
    const float* w    = (const float*)d_in[1];
    const float* bias = (const float*)d_in[2];
    float* out        = (float*)d_out;

    __half *dA = nullptr, *dB = nullptr;
    cudaGetSymbolAddress((void**)&dA, g_A);
    cudaGetSymbolAddress((void**)&dB, g_B);

    // 1) fused FWHT + W-conversion
    prep_kernel<<<TOKENS + WCONV_BLOCKS, 256>>>(x, (const float4*)w, dA, dB);

    // 2) GEMM (non-persistent: HW CTA overlap hides tile transitions)
    cudaFuncSetAttribute(gemm_kernel, cudaFuncAttributeMaxDynamicSharedMemorySize, SMEM_TOTAL);
    dim3 grid((TOKENS / BM) * (DOUT / BN));  // 4096 CTAs, group-swizzled 1D
    gemm_kernel<<<grid, NTHREADS, SMEM_TOTAL>>>(dA, dB, bias, out);
}

// round 14
// speedup vs baseline: 1.1086x; 1.0598x over previous
#include <cuda_runtime.h>
#include <cuda.h>
#include <cuda_fp16.h>
#include <cstdint>
#include <cstddef>

// ============================================================================
// Problem dims
// ============================================================================
#define TOKENS 8192
#define DIN    2048
#define DOUT   8192

// GEMM tiling — FP16 mma.sync m16n8k16, 4 warps x (64x64), 2 CTAs/SM
#define BM 128
#define BN 128
#define BK 64                    // 64 halves = 128B row = swizzle atom
#define NSTAGE 3
#define NK (DIN/BK)              // 32

#define NWARP_M 2
#define NWARP_N 2
#define WM (BM/NWARP_M)          // 64
#define WN (BN/NWARP_N)          // 64
#define NTHREADS 128             // 4 compute warps

#define A_STAGE_BYTES (BM*BK*2)              // 16384
#define B_STAGE_BYTES (BN*BK*2)              // 16384
#define STAGE_BYTES   (A_STAGE_BYTES + B_STAGE_BYTES)  // 32768
#define SMEM_TOTAL    (NSTAGE*STAGE_BYTES)   // 98304 -> 2 CTAs/SM

#define NCHUNK 8                 // 16B chunks per thread per stage (A and B each)

// ============================================================================
// Scratch
// ============================================================================
__device__ __half g_A[(size_t)TOKENS * DIN];   // 32 MiB, FWHT output (fp16)
__device__ __half g_B[(size_t)DOUT   * DIN];   // 32 MiB, W in fp16 (exact)

// ============================================================================
// Helpers
// ============================================================================
__device__ __forceinline__ uint32_t smem_to_u32(const void* p) {
    uint32_t a;
    asm("{ .reg .u64 t; cvta.to.shared.u64 t, %1; cvt.u32.u64 %0, t; }" : "=r"(a) : "l"(p));
    return a;
}

__device__ __forceinline__ void cpasync16(uint32_t dst, const __half* src) {
    asm volatile("cp.async.cg.shared.global [%0], [%1], 16;" :: "r"(dst), "l"(src));
}

__device__ __forceinline__ void ldsm_x4(uint32_t* r, uint32_t addr) {
    asm volatile("ldmatrix.sync.aligned.m8n8.x4.shared.b16 {%0,%1,%2,%3}, [%4];"
        : "=r"(r[0]), "=r"(r[1]), "=r"(r[2]), "=r"(r[3]) : "r"(addr));
}

__device__ __forceinline__ void mma_f16(float* c, const uint32_t* a, const uint32_t* b) {
    asm volatile(
        "mma.sync.aligned.m16n8k16.row.col.f32.f16.f16.f32 "
        "{%0,%1,%2,%3}, {%4,%5,%6,%7}, {%8,%9}, {%0,%1,%2,%3};"
        : "+f"(c[0]), "+f"(c[1]), "+f"(c[2]), "+f"(c[3])
        : "r"(a[0]), "r"(a[1]), "r"(a[2]), "r"(a[3]), "r"(b[0]), "r"(b[1]));
}

// ============================================================================
// Kernel 1 (fused prep): blocks [0, TOKENS) per-row FWHT -> fp16 g_A;
// blocks [TOKENS, TOKENS+WCONV_BLOCKS) convert W fp32 -> fp16 g_B.
// ============================================================================
#define WCONV_BLOCKS ((DOUT*DIN/4)/256)   // 16384 blocks, 1 float4 per thread

__global__ void __launch_bounds__(256) prep_kernel(const float* __restrict__ x,
                                                   const float4* __restrict__ w4,
                                                   __half* __restrict__ A,
                                                   __half* __restrict__ B) {
    if (blockIdx.x >= TOKENS) {
        size_t i = (size_t)(blockIdx.x - TOKENS) * 256 + threadIdx.x;
        float4 v = w4[i];
        __half2 p0 = __floats2half2_rn(v.x, v.y);
        __half2 p1 = __floats2half2_rn(v.z, v.w);
        __half2* dst = reinterpret_cast<__half2*>(B + i * 4);
        dst[0] = p0;
        dst[1] = p1;
        return;
    }
    __shared__ float s[DIN];
    const int t = threadIdx.x;
    const int lane = t & 31;
    const float* xr = x + (size_t)blockIdx.x * DIN;

    float v[8];
    #pragma unroll
    for (int e = 0; e < 8; e++) v[e] = xr[t + 256 * e];
    #pragma unroll
    for (int hb = 1; hb <= 4; hb <<= 1) {       // h = 256,512,1024
        #pragma unroll
        for (int e = 0; e < 8; e++) {
            if (!(e & hb)) {
                float a = v[e], b = v[e | hb];
                v[e] = a + b;
                v[e | hb] = a - b;
            }
        }
    }
    #pragma unroll
    for (int e = 0; e < 8; e++) s[t + 256 * e] = v[e];
    __syncthreads();
    {
        float4 f0 = *reinterpret_cast<const float4*>(&s[8 * t]);
        float4 f1 = *reinterpret_cast<const float4*>(&s[8 * t + 4]);
        v[0] = f0.x; v[1] = f0.y; v[2] = f0.z; v[3] = f0.w;
        v[4] = f1.x; v[5] = f1.y; v[6] = f1.z; v[7] = f1.w;
    }
    #pragma unroll
    for (int hb = 1; hb <= 4; hb <<= 1) {       // h = 1,2,4
        #pragma unroll
        for (int e = 0; e < 8; e++) {
            if (!(e & hb)) {
                float a = v[e], b = v[e | hb];
                v[e] = a + b;
                v[e | hb] = a - b;
            }
        }
    }
    #pragma unroll
    for (int mask = 1; mask <= 16; mask <<= 1) { // h = 8..128
        #pragma unroll
        for (int e = 0; e < 8; e++) {
            float o = __shfl_xor_sync(0xFFFFFFFFu, v[e], mask);
            v[e] = (lane & mask) ? (o - v[e]) : (v[e] + o);
        }
    }
    const float scale = 0.022097086912079608f;  // 1/sqrt(2048)
    __half2 h[4];
    #pragma unroll
    for (int e = 0; e < 4; e++)
        h[e] = __floats2half2_rn(v[2 * e] * scale, v[2 * e + 1] * scale);
    *reinterpret_cast<uint4*>(A + (size_t)blockIdx.x * DIN + 8 * t) =
        *reinterpret_cast<uint4*>(h);
}

// ============================================================================
// Kernel 2: FP16 GEMM — cp.async 3-stage + ldmatrix. The 16 per-thread
// LDGSTS of each stage are SPREAD across the 4 kk blocks (4 per kk, issued
// between that kk's ldmatrix and its MMA burst) so the LSU burst drains
// under the tensor bursts instead of colliding with the fragment loads.
//   out[t][o] = sum_k A[t][k] * W[o][k] + bias[o]
//   smem: physical_byte(row, colbyte) = row*128 + (colbyte ^ ((row&7)*16))
// ============================================================================
__global__ void __launch_bounds__(NTHREADS, 2)
gemm_kernel(const __half* __restrict__ Ag,
            const __half* __restrict__ Wg,
            const float* __restrict__ bias,
            float* __restrict__ out) {
    extern __shared__ char smem[];
    const uint32_t sb = smem_to_u32(smem);
    const int tid = threadIdx.x, wid = tid >> 5, lane = tid & 31;
    const int lr = lane >> 2, lc = lane & 3;

    // group-swizzled tile mapping (GROUP_M=8 for L2 locality)
    const int num_n = DOUT / BN;     // 64
    const int GROUP_M = 8;
    int bid = blockIdx.x;
    int per_grp = GROUP_M * num_n;   // 512
    int g = bid / per_grp;
    int pid_m = g * GROUP_M + (bid % per_grp) % GROUP_M;
    int pid_n = (bid % per_grp) / GROUP_M;
    const int m0 = pid_m * BM;
    const int n0 = pid_n * BN;

    // -------- cp.async base addresses (chunk j: +16j*DIN src, +2048j dst) ---
    const int r0 = tid >> 3, c16 = tid & 7;
    const __half* srcA0 = Ag + (size_t)(m0 + r0) * DIN + c16 * 8;
    const __half* srcB0 = Wg + (size_t)(n0 + r0) * DIN + c16 * 8;
    const uint32_t dst0 = (uint32_t)(r0 * 128 + ((c16 * 16) ^ ((r0 & 7) * 16)));

    // -------- prologue: fill stages 0..NSTAGE-2 ------------------------------
    #pragma unroll
    for (int pre = 0; pre < NSTAGE - 1; pre++) {
        const uint32_t stg = sb + pre * STAGE_BYTES;
        const int koff = pre * BK;
        #pragma unroll
        for (int j = 0; j < NCHUNK; j++)
            cpasync16(stg + dst0 + 2048 * j, srcA0 + (size_t)16 * j * DIN + koff);
        #pragma unroll
        for (int j = 0; j < NCHUNK; j++)
            cpasync16(stg + A_STAGE_BYTES + dst0 + 2048 * j,
                      srcB0 + (size_t)16 * j * DIN + koff);
        asm volatile("cp.async.commit_group;" ::: "memory");
    }

    // -------- ldmatrix lane addressing --------------------------------------
    const int wm0 = (wid & 1) * WM;      // 0/64
    const int wn0 = (wid >> 1) * WN;     // 0/64
    const int r8 = lane & 7;
    const uint32_t maskL = (uint32_t)(r8 * 16);
    const uint32_t aHi16 = (uint32_t)(((lane >> 4) & 1) * 16);
    const uint32_t aRowByte = (uint32_t)((wm0 + ((lane >> 3) & 1) * 8 + r8) * 128);
    const uint32_t bHi16 = (uint32_t)(((lane >> 3) & 1) * 16);
    const uint32_t bRowByte =
        (uint32_t)(A_STAGE_BYTES + (wn0 + ((lane >> 4) & 1) * 8 + r8) * 128);

    float acc[WM / 16][WN / 8][4];   // [4][8][4] = 128 regs
    #pragma unroll
    for (int mt = 0; mt < WM / 16; mt++)
        #pragma unroll
        for (int nt = 0; nt < WN / 8; nt++)
            #pragma unroll
            for (int q = 0; q < 4; q++) acc[mt][nt][q] = 0.0f;

    // -------- main loop ------------------------------------------------------
    int slot = 0;
    int slot2 = NSTAGE - 1;
    for (int ki = 0; ki < NK; ki++) {
        asm volatile("cp.async.wait_group %0;" :: "n"(NSTAGE - 2) : "memory");
        __syncthreads();

        const uint32_t stg = sb + slot * STAGE_BYTES;
        const uint32_t stg2 = sb + slot2 * STAGE_BYTES;
        const int nk2 = ki + NSTAGE - 1;
        const bool produce = (nk2 < NK);
        const int koff = nk2 * BK;

        #pragma unroll
        for (int kk = 0; kk < BK / 16; kk++) {
            const uint32_t aCol = ((uint32_t)(kk * 32) + aHi16) ^ maskL;
            const uint32_t bCol = ((uint32_t)(kk * 32) + bHi16) ^ maskL;
            uint32_t afr[WM / 16][4];
            uint32_t bfr[WN / 8][2];
            #pragma unroll
            for (int mt = 0; mt < WM / 16; mt++)
                ldsm_x4(afr[mt], stg + aRowByte + mt * 2048 + aCol);
            #pragma unroll
            for (int p = 0; p < WN / 16; p++)
                ldsm_x4(&bfr[2 * p][0], stg + bRowByte + p * 2048 + bCol);

            // spread producer: 2 A-chunks + 2 B-chunks per kk (16 total per ki)
            if (produce) {
                #pragma unroll
                for (int q = 0; q < 2; q++) {
                    const int j = 2 * kk + q;
                    cpasync16(stg2 + dst0 + 2048 * j,
                              srcA0 + (size_t)16 * j * DIN + koff);
                    cpasync16(stg2 + A_STAGE_BYTES + dst0 + 2048 * j,
                              srcB0 + (size_t)16 * j * DIN + koff);
                }
            }

            #pragma unroll
            for (int mt = 0; mt < WM / 16; mt++)
                #pragma unroll
                for (int nt = 0; nt < WN / 8; nt++)
                    mma_f16(acc[mt][nt], afr[mt], bfr[nt]);
        }

        asm volatile("cp.async.commit_group;" ::: "memory");

        if (++slot == NSTAGE) slot = 0;
        if (++slot2 == NSTAGE) slot2 = 0;
    }

    // -------- epilogue: bias + store ----------------------------------------
    #pragma unroll
    for (int mt = 0; mt < WM / 16; mt++) {
        const int row0 = m0 + wm0 + mt * 16 + lr;
        float* o0 = out + (size_t)row0 * DOUT;
        float* o1 = o0 + (size_t)8 * DOUT;
        #pragma unroll
        for (int nt = 0; nt < WN / 8; nt++) {
            const int col = n0 + wn0 + nt * 8 + 2 * lc;
            const float2 bv = *reinterpret_cast<const float2*>(&bias[col]);
            float2 v0, v1;
            v0.x = acc[mt][nt][0] + bv.x;  v0.y = acc[mt][nt][1] + bv.y;
            v1.x = acc[mt][nt][2] + bv.x;  v1.y = acc[mt][nt][3] + bv.y;
            *reinterpret_cast<float2*>(o0 + col) = v0;
            *reinterpret_cast<float2*>(o1 + col) = v1;
        }
    }
}

// ============================================================================
// Host launch
// ============================================================================
extern "C" void kernel_launch(void* const* d_in, const int* in_sizes, int n_in,
                              void* d_out, int out_size) {
    const float* x    = (const float*)d_in[0];
    const float* w    = (const float*)d_in[1];
    const float* bias = (const float*)d_in[2];
    float* out        = (float*)d_out;

    __half *dA = nullptr, *dB = nullptr;
    cudaGetSymbolAddress((void**)&dA, g_A);
    cudaGetSymbolAddress((void**)&dB, g_B);

    // 1) fused FWHT + W-conversion
    prep_kernel<<<TOKENS + WCONV_BLOCKS, 256>>>(x, (const float4*)w, dA, dB);

    // 2) GEMM
    cudaFuncSetAttribute(gemm_kernel, cudaFuncAttributeMaxDynamicSharedMemorySize, SMEM_TOTAL);
    dim3 grid((TOKENS / BM) * (DOUT / BN));  // 4096 CTAs, group-swizzled 1D
    gemm_kernel<<<grid, NTHREADS, SMEM_TOTAL>>>(dA, dB, bias, out);
}